// round 1
// baseline (speedup 1.0000x reference)
#include <cuda_runtime.h>

// NeighborlistVerletNsq: all-pairs PBC displacement + cutoff mask.
// Output layout (float32, element offsets, P = number of unique pairs):
//   [0P..1P)  i_pairs        [1P..2P) j_pairs
//   [2P..3P)  j_pairs        [3P..4P) i_pairs
//   [4P..5P)  d_m            [5P..6P) d_m
//   [6P..9P)  r_m (row-major [P,3])
//   [9P..12P) -r_m
//   [12P..13P) mask          [13P..14P) mask

__device__ __forceinline__ float wrap_pbc(float x, float L, float h) {
    // matches jnp.remainder(x + h, L) - h  (floor-mod), L > 0
    float t = x + h;
    float m = fmodf(t, L);       // exact trunc-mod, sign of t
    if (m < 0.0f) m += L;        // floor-mod fixup
    return m - h;
}

__global__ void __launch_bounds__(256)
nlist_kernel(const float* __restrict__ pos,
             const float* __restrict__ box,
             const int*   __restrict__ ip,
             const int*   __restrict__ jp,
             float*       __restrict__ out,
             int P)
{
    const int t  = blockIdx.x * blockDim.x + threadIdx.x;
    const int p0 = t * 4;
    if (p0 >= P) return;

    const float Lx = __ldg(box + 0);
    const float Ly = __ldg(box + 4);
    const float Lz = __ldg(box + 8);
    const float hx = 0.5f * Lx, hy = 0.5f * Ly, hz = 0.5f * Lz;
    const float CUTOFF = 0.5f;

    const size_t Ps = (size_t)P;

    if (p0 + 3 < P) {
        // ---- vector path: 4 pairs per thread, all 16B loads/stores ----
        const int4 i4 = *(const int4*)(ip + p0);
        const int4 j4 = *(const int4*)(jp + p0);
        const int is[4] = {i4.x, i4.y, i4.z, i4.w};
        const int js[4] = {j4.x, j4.y, j4.z, j4.w};

        float rx[4], ry[4], rz[4], dd[4], mk[4];
        #pragma unroll
        for (int k = 0; k < 4; k++) {
            const float* pi = pos + 3 * (size_t)is[k];
            const float* pj = pos + 3 * (size_t)js[k];
            float x = __ldg(pi + 0) - __ldg(pj + 0);
            float y = __ldg(pi + 1) - __ldg(pj + 1);
            float z = __ldg(pi + 2) - __ldg(pj + 2);
            x = wrap_pbc(x, Lx, hx);
            y = wrap_pbc(y, Ly, hy);
            z = wrap_pbc(z, Lz, hz);
            float d = sqrtf(x * x + y * y + z * z);
            bool m = (d <= CUTOFF);
            rx[k] = m ? x : 0.0f;
            ry[k] = m ? y : 0.0f;
            rz[k] = m ? z : 0.0f;
            dd[k] = m ? d : 0.0f;
            mk[k] = m ? 1.0f : 0.0f;
        }

        const float4 fi = make_float4((float)is[0], (float)is[1], (float)is[2], (float)is[3]);
        const float4 fj = make_float4((float)js[0], (float)js[1], (float)js[2], (float)js[3]);
        const float4 fd = make_float4(dd[0], dd[1], dd[2], dd[3]);
        const float4 fm = make_float4(mk[0], mk[1], mk[2], mk[3]);

        __stcs((float4*)(out +  0 * Ps + p0), fi);
        __stcs((float4*)(out +  1 * Ps + p0), fj);
        __stcs((float4*)(out +  2 * Ps + p0), fj);
        __stcs((float4*)(out +  3 * Ps + p0), fi);
        __stcs((float4*)(out +  4 * Ps + p0), fd);
        __stcs((float4*)(out +  5 * Ps + p0), fd);

        float* rpos = out + 6 * Ps + 3 * (size_t)p0;
        __stcs((float4*)(rpos + 0), make_float4(rx[0], ry[0], rz[0], rx[1]));
        __stcs((float4*)(rpos + 4), make_float4(ry[1], rz[1], rx[2], ry[2]));
        __stcs((float4*)(rpos + 8), make_float4(rz[2], rx[3], ry[3], rz[3]));

        float* rneg = out + 9 * Ps + 3 * (size_t)p0;
        __stcs((float4*)(rneg + 0), make_float4(-rx[0], -ry[0], -rz[0], -rx[1]));
        __stcs((float4*)(rneg + 4), make_float4(-ry[1], -rz[1], -rx[2], -ry[2]));
        __stcs((float4*)(rneg + 8), make_float4(-rz[2], -rx[3], -ry[3], -rz[3]));

        __stcs((float4*)(out + 12 * Ps + p0), fm);
        __stcs((float4*)(out + 13 * Ps + p0), fm);
    } else {
        // ---- scalar tail ----
        for (int p = p0; p < P; p++) {
            int i = __ldg(ip + p);
            int j = __ldg(jp + p);
            const float* pi = pos + 3 * (size_t)i;
            const float* pj = pos + 3 * (size_t)j;
            float x = __ldg(pi + 0) - __ldg(pj + 0);
            float y = __ldg(pi + 1) - __ldg(pj + 1);
            float z = __ldg(pi + 2) - __ldg(pj + 2);
            x = wrap_pbc(x, Lx, hx);
            y = wrap_pbc(y, Ly, hy);
            z = wrap_pbc(z, Lz, hz);
            float d = sqrtf(x * x + y * y + z * z);
            bool m = (d <= CUTOFF);
            float mx = m ? x : 0.0f, my = m ? y : 0.0f, mz = m ? z : 0.0f;
            float md = m ? d : 0.0f, mv = m ? 1.0f : 0.0f;

            out[ 0 * Ps + p] = (float)i;
            out[ 1 * Ps + p] = (float)j;
            out[ 2 * Ps + p] = (float)j;
            out[ 3 * Ps + p] = (float)i;
            out[ 4 * Ps + p] = md;
            out[ 5 * Ps + p] = md;
            out[ 6 * Ps + 3 * (size_t)p + 0] =  mx;
            out[ 6 * Ps + 3 * (size_t)p + 1] =  my;
            out[ 6 * Ps + 3 * (size_t)p + 2] =  mz;
            out[ 9 * Ps + 3 * (size_t)p + 0] = -mx;
            out[ 9 * Ps + 3 * (size_t)p + 1] = -my;
            out[ 9 * Ps + 3 * (size_t)p + 2] = -mz;
            out[12 * Ps + p] = mv;
            out[13 * Ps + p] = mv;
        }
    }
}

extern "C" void kernel_launch(void* const* d_in, const int* in_sizes, int n_in,
                              void* d_out, int out_size)
{
    const float* pos = (const float*)d_in[0];   // [N,3] float32
    const float* box = (const float*)d_in[1];   // [3,3] float32
    const int*   ip  = (const int*)d_in[2];     // [P] int32
    const int*   jp  = (const int*)d_in[3];     // [P] int32
    float* out = (float*)d_out;

    const int P = in_sizes[2];
    const int nthreads = (P + 3) / 4;
    const int block = 256;
    const int grid = (nthreads + block - 1) / block;
    nlist_kernel<<<grid, block>>>(pos, box, ip, jp, out, P);
}